// round 2
// baseline (speedup 1.0000x reference)
#include <cuda_runtime.h>
#include <cuda_bf16.h>
#include <math.h>

// GaussianMixture: B=8, N=131072, K=4, F=20, 5 EM iterations, REG_COVAR=1e-4.
// Fused E+M pass per iteration. Team-of-4-lanes per point (5 features/lane).

#define BB 8
#define NPTS 131072
#define KC 4
#define FDIM 20
#define FL 5                 // features per lane
#define CTAS_PER_B 37
#define THREADS 256
#define TEAMS_PER_CTA (THREADS/4)          // 64
#define TEAM_STRIDE (CTAS_PER_B*TEAMS_PER_CTA)  // 2368
#define NITERS_PT ((NPTS + TEAM_STRIDE - 1)/TEAM_STRIDE)  // 56

#define LOG2PI 1.8378770664093454f

// Output layout (concatenated fp32): resp, log_prob, means, cov, prior
#define RESP_OFF   0
#define LP_OFF     (BB*NPTS*KC)                    // 4194304
#define M_OFF      (2*BB*NPTS*KC)                  // 8388608
#define COV_OFF    (M_OFF + BB*KC*FDIM)            // 8389248
#define PRIOR_OFF  (COV_OFF + BB*KC*FDIM*FDIM)     // 8402048

// Sums layout per batch: [0,80) Sx  [80,160) S2x  [160,240) S2xx  [240,244) S1  [244,248) S2
__device__ float g_sums[BB][256];     // zero-initialized at module load; finalize re-zeroes
__device__ float g_c1[BB][KC][FDIM];  // -2*mu*ivar
__device__ float g_c2[BB][KC][FDIM];  // ivar
__device__ float g_C[BB][KC];         // -0.5*(F*log2pi + logdet + sum(ivar*mu^2))

// ---------------------------------------------------------------------------
// init: build e-step params for iteration 0 from input means / covariance,
// and zero the sums scratch. grid(8), block(128): warp k, lane f.
// ---------------------------------------------------------------------------
__global__ void gmm_init(const float* __restrict__ means,
                         const float* __restrict__ cov)
{
    int b = blockIdx.x;
    int k = threadIdx.x >> 5;
    int lane = threadIdx.x & 31;

    float mu = 0.f, var = 1.f;
    if (lane < FDIM) {
        mu  = means[(b*KC + k)*FDIM + lane];
        var = cov  [(b*KC + k)*FDIM + lane];
    }
    float ivv = (lane < FDIM) ? (1.0f/var) : 0.f;
    float ld  = (lane < FDIM) ? logf(var) : 0.f;
    float c0  = (lane < FDIM) ? (ivv*mu*mu) : 0.f;
    #pragma unroll
    for (int off = 1; off < 32; off <<= 1) {
        ld += __shfl_xor_sync(0xffffffffu, ld, off);
        c0 += __shfl_xor_sync(0xffffffffu, c0, off);
    }
    if (lane < FDIM) {
        g_c2[b][k][lane] = ivv;
        g_c1[b][k][lane] = -2.0f*mu*ivv;
    }
    if (lane == 0)
        g_C[b][k] = -0.5f*(FDIM*LOG2PI + ld + c0);

    for (int i = threadIdx.x; i < 256; i += blockDim.x)
        g_sums[b][i] = 0.f;
}

// ---------------------------------------------------------------------------
// accumulate: fused E-step + M-step sums. grid(37,8), block(256).
// 4-lane team per point: lane t handles features [5t,5t+5).
// ---------------------------------------------------------------------------
__global__ void __launch_bounds__(THREADS, 1)
gmm_accum(const float* __restrict__ data,
          float* __restrict__ out_resp,
          float* __restrict__ out_lp,
          int write_out)
{
    const int b    = blockIdx.y;
    const int tid  = threadIdx.x;
    const int lane = tid & 31;
    const int t    = lane & 3;
    const int team_g = blockIdx.x * TEAMS_PER_CTA + (tid >> 2);

    // per-lane e-step constants in registers
    float c1[KC][FL], c2[KC][FL], Ck[KC];
    #pragma unroll
    for (int k = 0; k < KC; k++) {
        Ck[k] = g_C[b][k];
        #pragma unroll
        for (int i = 0; i < FL; i++) {
            c1[k][i] = g_c1[b][k][t*FL + i];
            c2[k][i] = g_c2[b][k][t*FL + i];
        }
    }

    float Sx[KC][FL], S2x[KC][FL], S2xx[KC][FL];
    float S1[KC], S2[KC];
    #pragma unroll
    for (int k = 0; k < KC; k++) {
        S1[k] = 0.f; S2[k] = 0.f;
        #pragma unroll
        for (int i = 0; i < FL; i++) { Sx[k][i]=0.f; S2x[k][i]=0.f; S2xx[k][i]=0.f; }
    }

    const float* __restrict__ dptr = data + (size_t)b*NPTS*FDIM;

    for (int j = 0; j < NITERS_PT; j++) {
        const int p = team_g + j*TEAM_STRIDE;
        const bool valid = (p < NPTS);
        const float* xp = dptr + (size_t)p*FDIM + t*FL;

        float x[FL], xx[FL];
        #pragma unroll
        for (int i = 0; i < FL; i++) {
            x[i]  = valid ? __ldg(xp + i) : 0.f;
            xx[i] = x[i]*x[i];
        }

        // maha partial (quadratic form, constants folded) + team reduce
        float m2[KC];
        #pragma unroll
        for (int k = 0; k < KC; k++) {
            float a = 0.f;
            #pragma unroll
            for (int i = 0; i < FL; i++) {
                a = fmaf(c2[k][i], xx[i], a);
                a = fmaf(c1[k][i], x[i],  a);
            }
            a += __shfl_xor_sync(0xffffffffu, a, 1);
            a += __shfl_xor_sync(0xffffffffu, a, 2);
            m2[k] = a;
        }

        float lp[KC], pr[KC], s = 0.f;
        #pragma unroll
        for (int k = 0; k < KC; k++) {
            lp[k] = fmaf(-0.5f, m2[k], Ck[k]);       // full log_prob
            pr[k] = __expf(lp[k]) + 1e-8f;
            s += pr[k];
        }
        const float rinv = __fdividef(1.0f, s);
        float r[KC], r2[KC];
        #pragma unroll
        for (int k = 0; k < KC; k++) { r[k] = pr[k]*rinv; r2[k] = r[k]*r[k]; }

        if (valid) {
            if (t == 0) {
                #pragma unroll
                for (int k = 0; k < KC; k++) { S1[k] += r[k]; S2[k] += r2[k]; }
                if (write_out) {
                    const size_t o = ((size_t)b*NPTS + p)*KC;
                    *(float4*)(out_resp + o) = make_float4(r[0],r[1],r[2],r[3]);
                    *(float4*)(out_lp   + o) = make_float4(lp[0],lp[1],lp[2],lp[3]);
                }
            }
            #pragma unroll
            for (int k = 0; k < KC; k++) {
                #pragma unroll
                for (int i = 0; i < FL; i++) {
                    Sx[k][i]   = fmaf(r[k],  x[i],  Sx[k][i]);
                    S2x[k][i]  = fmaf(r2[k], x[i],  S2x[k][i]);
                    S2xx[k][i] = fmaf(r2[k], xx[i], S2xx[k][i]);
                }
            }
        }
    }

    // cross-team warp reduce (xor 4,8,16 keeps lane%4 slices aligned)
    #pragma unroll
    for (int off = 4; off < 32; off <<= 1) {
        #pragma unroll
        for (int k = 0; k < KC; k++) {
            #pragma unroll
            for (int i = 0; i < FL; i++) {
                Sx[k][i]   += __shfl_xor_sync(0xffffffffu, Sx[k][i],   off);
                S2x[k][i]  += __shfl_xor_sync(0xffffffffu, S2x[k][i],  off);
                S2xx[k][i] += __shfl_xor_sync(0xffffffffu, S2xx[k][i], off);
            }
            S1[k] += __shfl_xor_sync(0xffffffffu, S1[k], off);
            S2[k] += __shfl_xor_sync(0xffffffffu, S2[k], off);
        }
    }

    __shared__ float s_acc[256];
    for (int i = tid; i < 256; i += THREADS) s_acc[i] = 0.f;
    __syncthreads();

    if (lane < 4) {   // lane == t here; holds warp totals for its feature slice
        #pragma unroll
        for (int k = 0; k < KC; k++) {
            #pragma unroll
            for (int i = 0; i < FL; i++) {
                const int f = lane*FL + i;
                atomicAdd(&s_acc[       k*FDIM + f], Sx[k][i]);
                atomicAdd(&s_acc[ 80 +  k*FDIM + f], S2x[k][i]);
                atomicAdd(&s_acc[160 +  k*FDIM + f], S2xx[k][i]);
            }
        }
        if (lane == 0) {
            #pragma unroll
            for (int k = 0; k < KC; k++) {
                atomicAdd(&s_acc[240 + k], S1[k]);
                atomicAdd(&s_acc[244 + k], S2[k]);
            }
        }
    }
    __syncthreads();
    for (int i = tid; i < 248; i += THREADS)
        atomicAdd(&g_sums[b][i], s_acc[i]);
}

// ---------------------------------------------------------------------------
// finalize: M-step from sums -> new e-step params; re-zero sums.
// Last iteration also writes means/cov/prior outputs.
// grid(8), block(128): warp k, lane f.
// ---------------------------------------------------------------------------
__global__ void gmm_finalize(float* __restrict__ out_m,
                             float* __restrict__ out_cov,
                             float* __restrict__ out_prior,
                             int last)
{
    int b = blockIdx.x;
    int k = threadIdx.x >> 5;
    int lane = threadIdx.x & 31;

    const float S1 = g_sums[b][240 + k];
    const float S2 = g_sums[b][244 + k];

    float mu = 0.f, var = 1.f;
    if (lane < FDIM) {
        const float sx   = g_sums[b][       k*FDIM + lane];
        const float s2x  = g_sums[b][ 80 +  k*FDIM + lane];
        const float s2xx = g_sums[b][160 +  k*FDIM + lane];
        mu  = sx / S1;
        var = (s2xx - 2.0f*mu*s2x + mu*mu*S2) / S1;
        var = fmaxf(var, 1e-4f);
    }
    const float ivv = (lane < FDIM) ? (1.0f/var) : 0.f;
    float ld = (lane < FDIM) ? logf(var) : 0.f;
    float c0 = (lane < FDIM) ? (ivv*mu*mu) : 0.f;
    #pragma unroll
    for (int off = 1; off < 32; off <<= 1) {
        ld += __shfl_xor_sync(0xffffffffu, ld, off);
        c0 += __shfl_xor_sync(0xffffffffu, c0, off);
    }
    if (lane < FDIM) {
        g_c2[b][k][lane] = ivv;
        g_c1[b][k][lane] = -2.0f*mu*ivv;
    }
    if (lane == 0)
        g_C[b][k] = -0.5f*(FDIM*LOG2PI + ld + c0);

    if (last) {
        if (lane < FDIM)
            out_m[(b*KC + k)*FDIM + lane] = mu;
        if (lane == 0)
            out_prior[b*KC + k] = S1;
        // cov: diagonal var, zeros elsewhere
        #pragma unroll
        for (int i = 0; i < FDIM; i++) {
            const float vi = __shfl_sync(0xffffffffu, var, i);
            if (lane < FDIM)
                out_cov[(((size_t)(b*KC + k))*FDIM + i)*FDIM + lane] =
                    (lane == i) ? vi : 0.f;
        }
    }

    __syncthreads();           // all reads of g_sums done
    for (int i = threadIdx.x; i < 256; i += blockDim.x)
        g_sums[b][i] = 0.f;    // clean for next iteration / next launch
}

// ---------------------------------------------------------------------------
extern "C" void kernel_launch(void* const* d_in, const int* in_sizes, int n_in,
                              void* d_out, int out_size)
{
    (void)in_sizes; (void)n_in; (void)out_size;
    const float* data  = (const float*)d_in[0];
    const float* means = (const float*)d_in[1];
    const float* cov   = (const float*)d_in[2];
    float* out = (float*)d_out;

    float* out_resp  = out + RESP_OFF;
    float* out_lp    = out + LP_OFF;
    float* out_m     = out + M_OFF;
    float* out_cov   = out + COV_OFF;
    float* out_prior = out + PRIOR_OFF;

    gmm_init<<<BB, 128>>>(means, cov);
    for (int it = 0; it < 5; it++) {
        const int last = (it == 4);
        gmm_accum<<<dim3(CTAS_PER_B, BB), THREADS>>>(data, out_resp, out_lp, last);
        gmm_finalize<<<BB, 128>>>(out_m, out_cov, out_prior, last);
    }
}

// round 3
// speedup vs baseline: 1.2561x; 1.2561x over previous
#include <cuda_runtime.h>
#include <cuda_bf16.h>
#include <math.h>

// GaussianMixture: B=8, N=131072, K=4, F=20, 5 EM iterations, REG_COVAR=1e-4.
// Fused E+M pass per iteration. 4-lane team per point, K-SPLIT: lane t owns
// component k=t (all 20 features). Softmax via 2 shfl; 1 expf per lane-point.

#define BB 8
#define NPTS 131072
#define KC 4
#define FDIM 20
#define CTAS_PER_B 37
#define THREADS 256
#define TEAMS_PER_CTA (THREADS/4)                        // 64
#define TEAM_STRIDE (CTAS_PER_B*TEAMS_PER_CTA)           // 2368
#define NITERS_PT ((NPTS + TEAM_STRIDE - 1)/TEAM_STRIDE) // 56

#define LOG2PI 1.8378770664093454f

// Output layout (concatenated fp32): resp, log_prob, means, cov, prior
#define RESP_OFF   0
#define LP_OFF     (BB*NPTS*KC)
#define M_OFF      (2*BB*NPTS*KC)
#define COV_OFF    (M_OFF + BB*KC*FDIM)
#define PRIOR_OFF  (COV_OFF + BB*KC*FDIM*FDIM)

// Sums per batch: [0,80) Sx  [80,160) S2x  [160,240) S2xx  [240,244) S1  [244,248) S2
__device__ float g_sums[BB][256];     // zeroed at load; finalize re-zeroes
__device__ float g_c1[BB][KC][FDIM];  // -2*mu*ivar
__device__ float g_c2[BB][KC][FDIM];  // ivar
__device__ float g_C[BB][KC];         // -0.5*(F*log2pi + logdet + sum(ivar*mu^2))

// ---------------------------------------------------------------------------
__global__ void gmm_init(const float* __restrict__ means,
                         const float* __restrict__ cov)
{
    int b = blockIdx.x;
    int k = threadIdx.x >> 5;
    int lane = threadIdx.x & 31;

    float mu = 0.f, var = 1.f;
    if (lane < FDIM) {
        mu  = means[(b*KC + k)*FDIM + lane];
        var = cov  [(b*KC + k)*FDIM + lane];
    }
    float ivv = (lane < FDIM) ? (1.0f/var) : 0.f;
    float ld  = (lane < FDIM) ? logf(var) : 0.f;
    float c0  = (lane < FDIM) ? (ivv*mu*mu) : 0.f;
    #pragma unroll
    for (int off = 1; off < 32; off <<= 1) {
        ld += __shfl_xor_sync(0xffffffffu, ld, off);
        c0 += __shfl_xor_sync(0xffffffffu, c0, off);
    }
    if (lane < FDIM) {
        g_c2[b][k][lane] = ivv;
        g_c1[b][k][lane] = -2.0f*mu*ivv;
    }
    if (lane == 0)
        g_C[b][k] = -0.5f*(FDIM*LOG2PI + ld + c0);

    for (int i = threadIdx.x; i < 256; i += blockDim.x)
        g_sums[b][i] = 0.f;
}

// ---------------------------------------------------------------------------
// accumulate: grid(37,8), block(256), 2 CTAs/SM.
// lane t = lane&3 owns component k=t for its team's point.
// ---------------------------------------------------------------------------
__global__ void __launch_bounds__(THREADS, 2)
gmm_accum(const float* __restrict__ data,
          float* __restrict__ out_resp,
          float* __restrict__ out_lp,
          int write_out)
{
    const int b    = blockIdx.y;
    const int tid  = threadIdx.x;
    const int lane = tid & 31;
    const int t    = lane & 3;          // my component k
    const int team_g = blockIdx.x * TEAMS_PER_CTA + (tid >> 2);

    // loop-invariant constants for my k
    float c1[FDIM], c2[FDIM];
    #pragma unroll
    for (int f = 0; f < FDIM; f++) {
        c1[f] = g_c1[b][t][f];
        c2[f] = g_c2[b][t][f];
    }
    const float Ck = g_C[b][t];

    float Sx[FDIM], S2x[FDIM], S2xx[FDIM];
    float S1 = 0.f, S2 = 0.f;
    #pragma unroll
    for (int f = 0; f < FDIM; f++) { Sx[f]=0.f; S2x[f]=0.f; S2xx[f]=0.f; }

    const float* __restrict__ dptr = data + (size_t)b*NPTS*FDIM;

    for (int j = 0; j < NITERS_PT; j++) {
        const int p = team_g + j*TEAM_STRIDE;
        const bool valid = (p < NPTS);
        const int pc = valid ? p : 0;                   // clamp: safe load
        const float4* __restrict__ xp =
            (const float4*)(dptr + (size_t)pc*FDIM);    // 80B point, 16B aligned

        float x[FDIM];
        float a = 0.f;                                  // maha for my k
        #pragma unroll
        for (int c = 0; c < FDIM/4; c++) {
            const float4 v = __ldg(xp + c);
            x[4*c+0]=v.x; x[4*c+1]=v.y; x[4*c+2]=v.z; x[4*c+3]=v.w;
            #pragma unroll
            for (int e = 0; e < 4; e++) {
                const float xf = x[4*c+e];
                a = fmaf(c2[4*c+e], xf*xf, a);
                a = fmaf(c1[4*c+e], xf,    a);
            }
        }

        const float lp = fmaf(-0.5f, a, Ck);            // full log_prob for my k
        const float pr = __expf(lp) + 1e-8f;
        float s = pr;
        s += __shfl_xor_sync(0xffffffffu, s, 1);
        s += __shfl_xor_sync(0xffffffffu, s, 2);
        const float r  = __fdividef(pr, s);
        const float r2 = r*r;

        if (valid) {
            S1 += r; S2 += r2;
            #pragma unroll
            for (int f = 0; f < FDIM; f++) {
                const float xf = x[f];
                Sx[f]   = fmaf(r,  xf,    Sx[f]);
                S2x[f]  = fmaf(r2, xf,    S2x[f]);
                S2xx[f] = fmaf(r2, xf*xf, S2xx[f]);
            }
            if (write_out) {
                const size_t o = ((size_t)b*NPTS + p)*KC + t;
                out_resp[o] = r;          // coalesced: 32 consecutive floats/warp
                out_lp[o]   = lp;
            }
        }
    }

    // cross-team warp reduce (xor 4,8,16 keeps lane%4 == k alignment)
    #pragma unroll
    for (int off = 4; off < 32; off <<= 1) {
        #pragma unroll
        for (int f = 0; f < FDIM; f++) {
            Sx[f]   += __shfl_xor_sync(0xffffffffu, Sx[f],   off);
            S2x[f]  += __shfl_xor_sync(0xffffffffu, S2x[f],  off);
            S2xx[f] += __shfl_xor_sync(0xffffffffu, S2xx[f], off);
        }
        S1 += __shfl_xor_sync(0xffffffffu, S1, off);
        S2 += __shfl_xor_sync(0xffffffffu, S2, off);
    }

    __shared__ float s_acc[256];
    for (int i = tid; i < 256; i += THREADS) s_acc[i] = 0.f;
    __syncthreads();

    if (lane < 4) {     // lane == t: warp totals for component t, all features
        #pragma unroll
        for (int f = 0; f < FDIM; f++) {
            atomicAdd(&s_acc[       t*FDIM + f], Sx[f]);
            atomicAdd(&s_acc[ 80 +  t*FDIM + f], S2x[f]);
            atomicAdd(&s_acc[160 +  t*FDIM + f], S2xx[f]);
        }
        atomicAdd(&s_acc[240 + t], S1);
        atomicAdd(&s_acc[244 + t], S2);
    }
    __syncthreads();
    for (int i = tid; i < 248; i += THREADS)
        atomicAdd(&g_sums[b][i], s_acc[i]);
}

// ---------------------------------------------------------------------------
__global__ void gmm_finalize(float* __restrict__ out_m,
                             float* __restrict__ out_cov,
                             float* __restrict__ out_prior,
                             int last)
{
    int b = blockIdx.x;
    int k = threadIdx.x >> 5;
    int lane = threadIdx.x & 31;

    const float S1 = g_sums[b][240 + k];
    const float S2 = g_sums[b][244 + k];

    float mu = 0.f, var = 1.f;
    if (lane < FDIM) {
        const float sx   = g_sums[b][       k*FDIM + lane];
        const float s2x  = g_sums[b][ 80 +  k*FDIM + lane];
        const float s2xx = g_sums[b][160 +  k*FDIM + lane];
        mu  = sx / S1;
        var = (s2xx - 2.0f*mu*s2x + mu*mu*S2) / S1;
        var = fmaxf(var, 1e-4f);
    }
    const float ivv = (lane < FDIM) ? (1.0f/var) : 0.f;
    float ld = (lane < FDIM) ? logf(var) : 0.f;
    float c0 = (lane < FDIM) ? (ivv*mu*mu) : 0.f;
    #pragma unroll
    for (int off = 1; off < 32; off <<= 1) {
        ld += __shfl_xor_sync(0xffffffffu, ld, off);
        c0 += __shfl_xor_sync(0xffffffffu, c0, off);
    }
    if (lane < FDIM) {
        g_c2[b][k][lane] = ivv;
        g_c1[b][k][lane] = -2.0f*mu*ivv;
    }
    if (lane == 0)
        g_C[b][k] = -0.5f*(FDIM*LOG2PI + ld + c0);

    if (last) {
        if (lane < FDIM)
            out_m[(b*KC + k)*FDIM + lane] = mu;
        if (lane == 0)
            out_prior[b*KC + k] = S1;
        #pragma unroll
        for (int i = 0; i < FDIM; i++) {
            const float vi = __shfl_sync(0xffffffffu, var, i);
            if (lane < FDIM)
                out_cov[(((size_t)(b*KC + k))*FDIM + i)*FDIM + lane] =
                    (lane == i) ? vi : 0.f;
        }
    }

    __syncthreads();
    for (int i = threadIdx.x; i < 256; i += blockDim.x)
        g_sums[b][i] = 0.f;
}

// ---------------------------------------------------------------------------
extern "C" void kernel_launch(void* const* d_in, const int* in_sizes, int n_in,
                              void* d_out, int out_size)
{
    (void)in_sizes; (void)n_in; (void)out_size;
    const float* data  = (const float*)d_in[0];
    const float* means = (const float*)d_in[1];
    const float* cov   = (const float*)d_in[2];
    float* out = (float*)d_out;

    float* out_resp  = out + RESP_OFF;
    float* out_lp    = out + LP_OFF;
    float* out_m     = out + M_OFF;
    float* out_cov   = out + COV_OFF;
    float* out_prior = out + PRIOR_OFF;

    gmm_init<<<BB, 128>>>(means, cov);
    for (int it = 0; it < 5; it++) {
        const int last = (it == 4);
        gmm_accum<<<dim3(CTAS_PER_B, BB), THREADS>>>(data, out_resp, out_lp, last);
        gmm_finalize<<<BB, 128>>>(out_m, out_cov, out_prior, last);
    }
}

// round 4
// speedup vs baseline: 1.2938x; 1.0300x over previous
#include <cuda_runtime.h>
#include <cuda_bf16.h>
#include <math.h>

// GaussianMixture: B=8, N=131072, K=4, F=20, 5 EM iters, REG_COVAR=1e-4.
// K-split teams (lane t owns component t) + packed f32x2 FMA hot loop.

#define BB 8
#define NPTS 131072
#define KC 4
#define FDIM 20
#define NP2 (FDIM/2)            // 10 packed pairs
#define CTAS_PER_B 37
#define THREADS 256
#define TEAMS_PER_CTA (THREADS/4)                        // 64
#define TEAM_STRIDE (CTAS_PER_B*TEAMS_PER_CTA)           // 2368
#define NITERS_PT ((NPTS + TEAM_STRIDE - 1)/TEAM_STRIDE) // 56

#define LOG2PI 1.8378770664093454f

#define RESP_OFF   0
#define LP_OFF     (BB*NPTS*KC)
#define M_OFF      (2*BB*NPTS*KC)
#define COV_OFF    (M_OFF + BB*KC*FDIM)
#define PRIOR_OFF  (COV_OFF + BB*KC*FDIM*FDIM)

typedef unsigned long long u64;

__device__ __forceinline__ u64 pack2(float lo, float hi) {
    u64 d; asm("mov.b64 %0, {%1,%2};" : "=l"(d) : "f"(lo), "f"(hi)); return d;
}
__device__ __forceinline__ void unpack2(u64 v, float& lo, float& hi) {
    asm("mov.b64 {%0,%1}, %2;" : "=f"(lo), "=f"(hi) : "l"(v));
}
__device__ __forceinline__ u64 fma2(u64 a, u64 b, u64 c) {
    u64 d; asm("fma.rn.f32x2 %0, %1, %2, %3;" : "=l"(d) : "l"(a), "l"(b), "l"(c)); return d;
}
__device__ __forceinline__ u64 mul2(u64 a, u64 b) {
    u64 d; asm("mul.rn.f32x2 %0, %1, %2;" : "=l"(d) : "l"(a), "l"(b)); return d;
}

// Sums per batch: [0,80) Sx  [80,160) S2x  [160,240) S2xx  [240,244) S1  [244,248) S2
__device__ float g_sums[BB][256];
__device__ float g_c1[BB][KC][FDIM];  // -2*mu*ivar
__device__ float g_c2[BB][KC][FDIM];  // ivar
__device__ float g_C[BB][KC];         // -0.5*(F*log2pi + logdet + sum(ivar*mu^2))

// ---------------------------------------------------------------------------
__global__ void gmm_init(const float* __restrict__ means,
                         const float* __restrict__ cov)
{
    int b = blockIdx.x;
    int k = threadIdx.x >> 5;
    int lane = threadIdx.x & 31;

    float mu = 0.f, var = 1.f;
    if (lane < FDIM) {
        mu  = means[(b*KC + k)*FDIM + lane];
        var = cov  [(b*KC + k)*FDIM + lane];
    }
    float ivv = (lane < FDIM) ? (1.0f/var) : 0.f;
    float ld  = (lane < FDIM) ? logf(var) : 0.f;
    float c0  = (lane < FDIM) ? (ivv*mu*mu) : 0.f;
    #pragma unroll
    for (int off = 1; off < 32; off <<= 1) {
        ld += __shfl_xor_sync(0xffffffffu, ld, off);
        c0 += __shfl_xor_sync(0xffffffffu, c0, off);
    }
    if (lane < FDIM) {
        g_c2[b][k][lane] = ivv;
        g_c1[b][k][lane] = -2.0f*mu*ivv;
    }
    if (lane == 0)
        g_C[b][k] = -0.5f*(FDIM*LOG2PI + ld + c0);

    for (int i = threadIdx.x; i < 256; i += blockDim.x)
        g_sums[b][i] = 0.f;
}

// ---------------------------------------------------------------------------
// accumulate: grid(37,8), block(256), 2 CTAs/SM. Packed f32x2 hot loop.
// ---------------------------------------------------------------------------
struct AccumState {
    u64 Sx[NP2], S2x[NP2], S2xx[NP2];
    float S1, S2;
};

__device__ __forceinline__ void point_body(
    const u64* __restrict__ xp,          // 10 packed f32 pairs (80B point)
    const u64* c1, const u64* c2, float Ck,
    AccumState& st,
    float* out_resp, float* out_lp, size_t out_o, int write_out)
{
    // ---- phase A: maha (load point, packed quad form) ----
    u64 a2 = 0;   // packed accumulator, bits of (0.f,0.f)
    #pragma unroll
    for (int i = 0; i < NP2; i++) {
        const u64 x2 = __ldg(xp + i);
        const u64 xx = mul2(x2, x2);
        a2 = fma2(c2[i], xx, a2);
        a2 = fma2(c1[i], x2, a2);
    }
    float alo, ahi; unpack2(a2, alo, ahi);
    const float a = alo + ahi;

    const float lp = fmaf(-0.5f, a, Ck);
    const float pr = __expf(lp) + 1e-8f;
    float s = pr;
    s += __shfl_xor_sync(0xffffffffu, s, 1);
    s += __shfl_xor_sync(0xffffffffu, s, 2);
    const float r  = __fdividef(pr, s);
    const float r2 = r*r;

    st.S1 += r; st.S2 += r2;
    const u64 rr   = pack2(r,  r);
    const u64 r2r2 = pack2(r2, r2);

    // ---- phase B: reload point (L1 hit), accumulate ----
    #pragma unroll
    for (int i = 0; i < NP2; i++) {
        const u64 x2 = __ldg(xp + i);
        const u64 xx = mul2(x2, x2);
        st.Sx[i]   = fma2(rr,   x2, st.Sx[i]);
        st.S2x[i]  = fma2(r2r2, x2, st.S2x[i]);
        st.S2xx[i] = fma2(r2r2, xx, st.S2xx[i]);
    }

    if (write_out) {
        out_resp[out_o] = r;
        out_lp[out_o]   = lp;
    }
}

__global__ void __launch_bounds__(THREADS, 2)
gmm_accum(const float* __restrict__ data,
          float* __restrict__ out_resp,
          float* __restrict__ out_lp,
          int write_out)
{
    const int b    = blockIdx.y;
    const int tid  = threadIdx.x;
    const int lane = tid & 31;
    const int t    = lane & 3;          // my component k
    const int team_g = blockIdx.x * TEAMS_PER_CTA + (tid >> 2);

    u64 c1[NP2], c2[NP2];
    #pragma unroll
    for (int i = 0; i < NP2; i++) {
        c1[i] = pack2(g_c1[b][t][2*i], g_c1[b][t][2*i+1]);
        c2[i] = pack2(g_c2[b][t][2*i], g_c2[b][t][2*i+1]);
    }
    const float Ck = g_C[b][t];

    AccumState st;
    st.S1 = 0.f; st.S2 = 0.f;
    #pragma unroll
    for (int i = 0; i < NP2; i++) { st.Sx[i]=0; st.S2x[i]=0; st.S2xx[i]=0; }

    const float* __restrict__ dptr = data + (size_t)b*NPTS*FDIM;

    // full iterations: p = team_g + j*TEAM_STRIDE < NPTS guaranteed for j<55
    #pragma unroll 1
    for (int j = 0; j < NITERS_PT-1; j++) {
        const int p = team_g + j*TEAM_STRIDE;
        point_body((const u64*)(dptr + (size_t)p*FDIM), c1, c2, Ck, st,
                   out_resp, out_lp, ((size_t)b*NPTS + p)*KC + t, write_out);
    }
    { // tail
        const int p = team_g + (NITERS_PT-1)*TEAM_STRIDE;
        if (p < NPTS)
            point_body((const u64*)(dptr + (size_t)p*FDIM), c1, c2, Ck, st,
                       out_resp, out_lp, ((size_t)b*NPTS + p)*KC + t, write_out);
    }

    // unpack accumulators to scalars for the reduction
    float Sxs[FDIM], S2xs[FDIM], S2xxs[FDIM];
    #pragma unroll
    for (int i = 0; i < NP2; i++) {
        unpack2(st.Sx[i],   Sxs[2*i],   Sxs[2*i+1]);
        unpack2(st.S2x[i],  S2xs[2*i],  S2xs[2*i+1]);
        unpack2(st.S2xx[i], S2xxs[2*i], S2xxs[2*i+1]);
    }
    float S1 = st.S1, S2 = st.S2;

    #pragma unroll
    for (int off = 4; off < 32; off <<= 1) {
        #pragma unroll
        for (int f = 0; f < FDIM; f++) {
            Sxs[f]   += __shfl_xor_sync(0xffffffffu, Sxs[f],   off);
            S2xs[f]  += __shfl_xor_sync(0xffffffffu, S2xs[f],  off);
            S2xxs[f] += __shfl_xor_sync(0xffffffffu, S2xxs[f], off);
        }
        S1 += __shfl_xor_sync(0xffffffffu, S1, off);
        S2 += __shfl_xor_sync(0xffffffffu, S2, off);
    }

    __shared__ float s_acc[256];
    for (int i = tid; i < 256; i += THREADS) s_acc[i] = 0.f;
    __syncthreads();

    if (lane < 4) {
        #pragma unroll
        for (int f = 0; f < FDIM; f++) {
            atomicAdd(&s_acc[       t*FDIM + f], Sxs[f]);
            atomicAdd(&s_acc[ 80 +  t*FDIM + f], S2xs[f]);
            atomicAdd(&s_acc[160 +  t*FDIM + f], S2xxs[f]);
        }
        atomicAdd(&s_acc[240 + t], S1);
        atomicAdd(&s_acc[244 + t], S2);
    }
    __syncthreads();
    for (int i = tid; i < 248; i += THREADS)
        atomicAdd(&g_sums[b][i], s_acc[i]);
}

// ---------------------------------------------------------------------------
__global__ void gmm_finalize(float* __restrict__ out_m,
                             float* __restrict__ out_cov,
                             float* __restrict__ out_prior,
                             int last)
{
    int b = blockIdx.x;
    int k = threadIdx.x >> 5;
    int lane = threadIdx.x & 31;

    const float S1 = g_sums[b][240 + k];
    const float S2 = g_sums[b][244 + k];

    float mu = 0.f, var = 1.f;
    if (lane < FDIM) {
        const float sx   = g_sums[b][       k*FDIM + lane];
        const float s2x  = g_sums[b][ 80 +  k*FDIM + lane];
        const float s2xx = g_sums[b][160 +  k*FDIM + lane];
        mu  = sx / S1;
        var = (s2xx - 2.0f*mu*s2x + mu*mu*S2) / S1;
        var = fmaxf(var, 1e-4f);
    }
    const float ivv = (lane < FDIM) ? (1.0f/var) : 0.f;
    float ld = (lane < FDIM) ? logf(var) : 0.f;
    float c0 = (lane < FDIM) ? (ivv*mu*mu) : 0.f;
    #pragma unroll
    for (int off = 1; off < 32; off <<= 1) {
        ld += __shfl_xor_sync(0xffffffffu, ld, off);
        c0 += __shfl_xor_sync(0xffffffffu, c0, off);
    }
    if (lane < FDIM) {
        g_c2[b][k][lane] = ivv;
        g_c1[b][k][lane] = -2.0f*mu*ivv;
    }
    if (lane == 0)
        g_C[b][k] = -0.5f*(FDIM*LOG2PI + ld + c0);

    if (last) {
        if (lane < FDIM)
            out_m[(b*KC + k)*FDIM + lane] = mu;
        if (lane == 0)
            out_prior[b*KC + k] = S1;
        #pragma unroll
        for (int i = 0; i < FDIM; i++) {
            const float vi = __shfl_sync(0xffffffffu, var, i);
            if (lane < FDIM)
                out_cov[(((size_t)(b*KC + k))*FDIM + i)*FDIM + lane] =
                    (lane == i) ? vi : 0.f;
        }
    }

    __syncthreads();
    for (int i = threadIdx.x; i < 256; i += blockDim.x)
        g_sums[b][i] = 0.f;
}

// ---------------------------------------------------------------------------
extern "C" void kernel_launch(void* const* d_in, const int* in_sizes, int n_in,
                              void* d_out, int out_size)
{
    (void)in_sizes; (void)n_in; (void)out_size;
    const float* data  = (const float*)d_in[0];
    const float* means = (const float*)d_in[1];
    const float* cov   = (const float*)d_in[2];
    float* out = (float*)d_out;

    float* out_resp  = out + RESP_OFF;
    float* out_lp    = out + LP_OFF;
    float* out_m     = out + M_OFF;
    float* out_cov   = out + COV_OFF;
    float* out_prior = out + PRIOR_OFF;

    gmm_init<<<BB, 128>>>(means, cov);
    for (int it = 0; it < 5; it++) {
        const int last = (it == 4);
        gmm_accum<<<dim3(CTAS_PER_B, BB), THREADS>>>(data, out_resp, out_lp, last);
        gmm_finalize<<<BB, 128>>>(out_m, out_cov, out_prior, last);
    }
}

// round 5
// speedup vs baseline: 2.0183x; 1.5600x over previous
#include <cuda_runtime.h>
#include <cuda_bf16.h>
#include <math.h>

// GaussianMixture: B=8, N=131072, K=4, F=20, 5 EM iters, REG_COVAR=1e-4.
// Quad per point; lane t loads features f ≡ t (mod 4) (5 floats, once).
// Math packed 2-wide ACROSS COMPONENTS (f32x2). M-step fused into next
// accum's prologue (double-buffered sums) — 6 launches total.

#define BB 8
#define NPTS 131072
#define KC 4
#define FDIM 20
#define NSL 5                      // feature slots per lane: f = t + 4*i
#define CTAS_PER_B 37
#define THREADS 256
#define TEAMS_PER_CTA (THREADS/4)                 // 64
#define TEAM_STRIDE (CTAS_PER_B*TEAMS_PER_CTA)    // 2368
#define LOG2PI 1.8378770664093454f

#define RESP_OFF   0
#define LP_OFF     (BB*NPTS*KC)
#define M_OFF      (2*BB*NPTS*KC)
#define COV_OFF    (M_OFF + BB*KC*FDIM)
#define PRIOR_OFF  (COV_OFF + BB*KC*FDIM*FDIM)

typedef unsigned long long u64;

__device__ __forceinline__ u64 pack2(float lo, float hi) {
    u64 d; asm("mov.b64 %0, {%1,%2};" : "=l"(d) : "f"(lo), "f"(hi)); return d;
}
__device__ __forceinline__ void unpack2(u64 v, float& lo, float& hi) {
    asm("mov.b64 {%0,%1}, %2;" : "=f"(lo), "=f"(hi) : "l"(v));
}
__device__ __forceinline__ u64 fma2(u64 a, u64 b, u64 c) {
    u64 d; asm("fma.rn.f32x2 %0, %1, %2, %3;" : "=l"(d) : "l"(a), "l"(b), "l"(c)); return d;
}
__device__ __forceinline__ u64 mul2(u64 a, u64 b) {
    u64 d; asm("mul.rn.f32x2 %0, %1, %2;" : "=l"(d) : "l"(a), "l"(b)); return d;
}
__device__ __forceinline__ u64 add2(u64 a, u64 b) {
    u64 d; asm("add.rn.f32x2 %0, %1, %2;" : "=l"(d) : "l"(a), "l"(b)); return d;
}
__device__ __forceinline__ u64 shfl_xor64(u64 v, int m) {
    return __shfl_xor_sync(0xffffffffu, v, m);
}

// Double-buffered sums: slot it holds results of iteration it.
// Layout per (it,b): [0,80) Sx  [80,160) S2x  [160,240) S2xx  [240,244) S1  [244,248) S2
__device__ float g_sums[5][BB][256];   // zero at load; gmm_final re-zeroes

struct Consts {
    u64 c1A[NSL], c1B[NSL], c2A[NSL], c2B[NSL];  // packed: A=(comp t, t^1), B=(t^2, t^3)
    float Ck;                                     // for my component t only
};

// ---------------------------------------------------------------------------
// accum: grid(37,8), block(256), 2 CTAs/SM.
// it: EM iteration index. it==0 uses input means/cov; else g_sums[it-1].
// ---------------------------------------------------------------------------
__global__ void __launch_bounds__(THREADS, 2)
gmm_accum(const float* __restrict__ data,
          const float* __restrict__ means,
          const float* __restrict__ covv,
          float* __restrict__ out_resp,
          float* __restrict__ out_lp,
          int it, int write_out)
{
    const int b    = blockIdx.y;
    const int tid  = threadIdx.x;
    const int lane = tid & 31;
    const int t    = lane & 3;                    // my component & feature phase
    const int team_g = blockIdx.x * TEAMS_PER_CTA + (tid >> 2);

    // ---- prologue: derive e-step constants (fused M-step of prev iter) ----
    Consts cst;
    {
        float c1s[KC][NSL], c2s[KC][NSL], ldp[KC];
        #pragma unroll
        for (int jj = 0; jj < KC; jj++) {
            const int c = t ^ jj;
            ldp[jj] = 0.f;
            #pragma unroll
            for (int i = 0; i < NSL; i++) {
                const int f = t + 4*i;
                float mu, var;
                if (it == 0) {
                    mu  = means[(b*KC + c)*FDIM + f];
                    var = covv [(b*KC + c)*FDIM + f];
                } else {
                    const float* s = g_sums[it-1][b];
                    const float S1c = s[240 + c], S2c = s[244 + c];
                    const float sx   = s[        c*FDIM + f];
                    const float s2x  = s[ 80 +   c*FDIM + f];
                    const float s2xx = s[160 +   c*FDIM + f];
                    mu  = sx / S1c;
                    var = (s2xx - 2.f*mu*s2x + mu*mu*S2c) / S1c;
                    var = fmaxf(var, 1e-4f);
                }
                const float iv = 1.f / var;
                c2s[jj][i] = iv;
                c1s[jj][i] = -2.f*mu*iv;
                ldp[jj] += __logf(var) + iv*mu*mu;
            }
        }
        #pragma unroll
        for (int i = 0; i < NSL; i++) {
            cst.c1A[i] = pack2(c1s[0][i], c1s[1][i]);
            cst.c1B[i] = pack2(c1s[2][i], c1s[3][i]);
            cst.c2A[i] = pack2(c2s[0][i], c2s[1][i]);
            cst.c2B[i] = pack2(c2s[2][i], c2s[3][i]);
        }
        // quad reduce-scatter of logdet + ivar*mu^2 partials -> my component
        u64 sld = add2(pack2(ldp[0], ldp[1]), shfl_xor64(pack2(ldp[2], ldp[3]), 2));
        float llo, lhi; unpack2(sld, llo, lhi);
        const float ld_self = llo + __shfl_xor_sync(0xffffffffu, lhi, 1);
        cst.Ck = -0.5f*(FDIM*LOG2PI + ld_self);
    }

    // ---- accumulators, k-packed ----
    u64 SxA[NSL], SxB[NSL], S2xA[NSL], S2xB[NSL], S2xxA[NSL], S2xxB[NSL];
    float S1 = 0.f, S2 = 0.f;
    #pragma unroll
    for (int i = 0; i < NSL; i++) {
        SxA[i]=0; SxB[i]=0; S2xA[i]=0; S2xB[i]=0; S2xxA[i]=0; S2xxB[i]=0;
    }

    const float* __restrict__ xptr = data + (size_t)b*NPTS*FDIM + t;
    float* __restrict__ orp = out_resp + (size_t)b*NPTS*KC + t;
    float* __restrict__ olp = out_lp   + (size_t)b*NPTS*KC + t;

    // body macro-ish lambda
    auto body = [&](const float x[NSL], int p) {
        u64 aA = 0, aB = 0;
        #pragma unroll
        for (int i = 0; i < NSL; i++) {
            const float xf = x[i], xxf = xf*xf;
            const u64 xp  = pack2(xf,  xf);
            const u64 xxp = pack2(xxf, xxf);
            aA = fma2(cst.c2A[i], xxp, aA);
            aA = fma2(cst.c1A[i], xp,  aA);
            aB = fma2(cst.c2B[i], xxp, aB);
            aB = fma2(cst.c1B[i], xp,  aB);
        }
        // reduce-scatter: full maha for my component
        u64 sA = add2(aA, shfl_xor64(aB, 2));
        float slo, shi; unpack2(sA, slo, shi);
        const float a_self = slo + __shfl_xor_sync(0xffffffffu, shi, 1);

        const float lp = fmaf(-0.5f, a_self, cst.Ck);
        const float pr = __expf(lp) + 1e-8f;
        const float p1 = __shfl_xor_sync(0xffffffffu, pr, 1);
        const u64 prA = pack2(pr, p1);
        const u64 prB = shfl_xor64(prA, 2);
        float q2, q3; unpack2(prB, q2, q3);
        const float s = (pr + p1) + (q2 + q3);
        const float rinv = __fdividef(1.f, s);
        const u64 rinv2 = pack2(rinv, rinv);
        const u64 rA = mul2(prA, rinv2), rB = mul2(prB, rinv2);
        const u64 r2A = mul2(rA, rA),    r2B = mul2(rB, rB);
        float r0, r1f; unpack2(rA, r0, r1f);
        S1 += r0; S2 += r0*r0;

        #pragma unroll
        for (int i = 0; i < NSL; i++) {
            const float xf = x[i], xxf = xf*xf;
            const u64 xp  = pack2(xf,  xf);
            const u64 xxp = pack2(xxf, xxf);
            SxA[i]   = fma2(rA,  xp,  SxA[i]);
            SxB[i]   = fma2(rB,  xp,  SxB[i]);
            S2xA[i]  = fma2(r2A, xp,  S2xA[i]);
            S2xB[i]  = fma2(r2B, xp,  S2xB[i]);
            S2xxA[i] = fma2(r2A, xxp, S2xxA[i]);
            S2xxB[i] = fma2(r2B, xxp, S2xxB[i]);
        }
        if (write_out) {
            orp[(size_t)p*KC] = r0;
            olp[(size_t)p*KC] = lp;
        }
    };

    // ---- main loop with 1-point prefetch ----
    int p = team_g;
    float x[NSL], xn[NSL];
    #pragma unroll
    for (int i = 0; i < NSL; i++)
        x[i] = __ldg(xptr + (size_t)p*FDIM + 4*i);

    #pragma unroll 1
    for (int j = 0; j < 54; j++) {                 // j = 0..53, p always valid
        const int pn = p + TEAM_STRIDE;
        #pragma unroll
        for (int i = 0; i < NSL; i++)
            xn[i] = __ldg(xptr + (size_t)pn*FDIM + 4*i);
        body(x, p);
        #pragma unroll
        for (int i = 0; i < NSL; i++) x[i] = xn[i];
        p = pn;
    }
    // j = 54 (valid); prefetch j=55 clamped (validity uniform per CTA)
    {
        const int p55 = p + TEAM_STRIDE;
        const int pnc = (p55 < NPTS) ? p55 : 0;
        #pragma unroll
        for (int i = 0; i < NSL; i++)
            xn[i] = __ldg(xptr + (size_t)pnc*FDIM + 4*i);
        body(x, p);
        #pragma unroll
        for (int i = 0; i < NSL; i++) x[i] = xn[i];
        p = p55;
    }
    if (p < NPTS) body(x, p);                      // tail, uniform per CTA

    // ---- cross-team warp reduce (offsets 4,8,16 keep t alignment) ----
    #pragma unroll
    for (int off = 4; off < 32; off <<= 1) {
        #pragma unroll
        for (int i = 0; i < NSL; i++) {
            SxA[i]   = add2(SxA[i],   shfl_xor64(SxA[i],   off));
            SxB[i]   = add2(SxB[i],   shfl_xor64(SxB[i],   off));
            S2xA[i]  = add2(S2xA[i],  shfl_xor64(S2xA[i],  off));
            S2xB[i]  = add2(S2xB[i],  shfl_xor64(S2xB[i],  off));
            S2xxA[i] = add2(S2xxA[i], shfl_xor64(S2xxA[i], off));
            S2xxB[i] = add2(S2xxB[i], shfl_xor64(S2xxB[i], off));
        }
        S1 += __shfl_xor_sync(0xffffffffu, S1, off);
        S2 += __shfl_xor_sync(0xffffffffu, S2, off);
    }

    __shared__ float s_acc[256];
    for (int i = tid; i < 256; i += THREADS) s_acc[i] = 0.f;
    __syncthreads();

    if (lane < 4) {   // lane == t; relative->absolute component mapping
        #pragma unroll
        for (int i = 0; i < NSL; i++) {
            const int f = t + 4*i;
            float lo, hi;
            unpack2(SxA[i], lo, hi);
            atomicAdd(&s_acc[(t  )*FDIM + f], lo);
            atomicAdd(&s_acc[(t^1)*FDIM + f], hi);
            unpack2(SxB[i], lo, hi);
            atomicAdd(&s_acc[(t^2)*FDIM + f], lo);
            atomicAdd(&s_acc[(t^3)*FDIM + f], hi);
            unpack2(S2xA[i], lo, hi);
            atomicAdd(&s_acc[80 + (t  )*FDIM + f], lo);
            atomicAdd(&s_acc[80 + (t^1)*FDIM + f], hi);
            unpack2(S2xB[i], lo, hi);
            atomicAdd(&s_acc[80 + (t^2)*FDIM + f], lo);
            atomicAdd(&s_acc[80 + (t^3)*FDIM + f], hi);
            unpack2(S2xxA[i], lo, hi);
            atomicAdd(&s_acc[160 + (t  )*FDIM + f], lo);
            atomicAdd(&s_acc[160 + (t^1)*FDIM + f], hi);
            unpack2(S2xxB[i], lo, hi);
            atomicAdd(&s_acc[160 + (t^2)*FDIM + f], lo);
            atomicAdd(&s_acc[160 + (t^3)*FDIM + f], hi);
        }
        atomicAdd(&s_acc[240 + t], S1);
        atomicAdd(&s_acc[244 + t], S2);
    }
    __syncthreads();
    for (int i = tid; i < 248; i += THREADS)
        atomicAdd(&g_sums[it][b][i], s_acc[i]);
}

// ---------------------------------------------------------------------------
// final: write means/cov/prior from g_sums[4]; re-zero all sum slots.
// grid(8), block(128): warp k, lane f.
// ---------------------------------------------------------------------------
__global__ void gmm_final(float* __restrict__ out_m,
                          float* __restrict__ out_cov,
                          float* __restrict__ out_prior)
{
    const int b = blockIdx.x;
    const int k = threadIdx.x >> 5;
    const int lane = threadIdx.x & 31;
    const float* s = g_sums[4][b];

    const float S1 = s[240 + k];
    const float S2 = s[244 + k];
    float mu = 0.f, var = 1.f;
    if (lane < FDIM) {
        const float sx   = s[        k*FDIM + lane];
        const float s2x  = s[ 80 +   k*FDIM + lane];
        const float s2xx = s[160 +   k*FDIM + lane];
        mu  = sx / S1;
        var = (s2xx - 2.f*mu*s2x + mu*mu*S2) / S1;
        var = fmaxf(var, 1e-4f);
        out_m[(b*KC + k)*FDIM + lane] = mu;
    }
    if (lane == 0) out_prior[b*KC + k] = S1;
    #pragma unroll
    for (int i = 0; i < FDIM; i++) {
        const float vi = __shfl_sync(0xffffffffu, var, i);
        if (lane < FDIM)
            out_cov[(((size_t)(b*KC + k))*FDIM + i)*FDIM + lane] =
                (lane == i) ? vi : 0.f;
    }

    __syncthreads();   // all reads of g_sums[4] done before zeroing
    for (int itt = 0; itt < 5; itt++)
        for (int i = threadIdx.x; i < 256; i += blockDim.x)
            g_sums[itt][b][i] = 0.f;
}

// ---------------------------------------------------------------------------
extern "C" void kernel_launch(void* const* d_in, const int* in_sizes, int n_in,
                              void* d_out, int out_size)
{
    (void)in_sizes; (void)n_in; (void)out_size;
    const float* data  = (const float*)d_in[0];
    const float* means = (const float*)d_in[1];
    const float* cov   = (const float*)d_in[2];
    float* out = (float*)d_out;

    float* out_resp  = out + RESP_OFF;
    float* out_lp    = out + LP_OFF;
    float* out_m     = out + M_OFF;
    float* out_cov   = out + COV_OFF;
    float* out_prior = out + PRIOR_OFF;

    for (int it = 0; it < 5; it++)
        gmm_accum<<<dim3(CTAS_PER_B, BB), THREADS>>>(
            data, means, cov, out_resp, out_lp, it, (it == 4) ? 1 : 0);
    gmm_final<<<BB, 128>>>(out_m, out_cov, out_prior);
}